// round 5
// baseline (speedup 1.0000x reference)
#include <cuda_runtime.h>
#include <cuda_bf16.h>
#include <cstdint>
#include <math.h>

#define B_TOK 8192
#define HDIM  7168
#define NEXP  256
#define NTOPK 8

#define BM 128
#define BN 128
#define BK 32
#define NT (HDIM / BK)          // 224

#define STRIDE 40               // smem row stride in bf16 elems (pad 8)
#define TILE_E (128 * STRIDE)   // 5120 elems per tile
#define OFF_AHI 0
#define OFF_ALO (1 * TILE_E)
#define OFF_BHI (2 * TILE_E)
#define OFF_BLO (3 * TILE_E)
#define STAGE_BYTES (4 * TILE_E * 2)          // 40960
#define SMEM_DYN (2 * STAGE_BYTES)            // 81920

// ---- device scratch (no cudaMalloc allowed) ----
__device__ float         g_logits[(size_t)B_TOK * NEXP];
__device__ __nv_bfloat16 g_wt_hi[(size_t)NEXP * HDIM];   // W^T hi  [E][H]
__device__ __nv_bfloat16 g_wt_lo[(size_t)NEXP * HDIM];   // W^T lo  [E][H]

__device__ __forceinline__ uint32_t smem_u32(const void* p) {
    uint32_t a;
    asm("{ .reg .u64 t; cvta.to.shared.u64 t, %1; cvt.u32.u64 %0, t; }" : "=r"(a) : "l"(p));
    return a;
}

#define LDSM_X4(d, addr)                                                        \
    asm volatile("ldmatrix.sync.aligned.m8n8.x4.shared.b16 {%0,%1,%2,%3}, [%4];"\
        : "=r"((d)[0]), "=r"((d)[1]), "=r"((d)[2]), "=r"((d)[3]) : "r"(addr))

#define MMA_BF16(c, a, b)                                                       \
    asm volatile("mma.sync.aligned.m16n8k16.row.col.f32.bf16.bf16.f32 "         \
        "{%0,%1,%2,%3}, {%4,%5,%6,%7}, {%8,%9}, {%0,%1,%2,%3};"                 \
        : "+f"((c)[0]), "+f"((c)[1]), "+f"((c)[2]), "+f"((c)[3])                \
        : "r"((a)[0]), "r"((a)[1]), "r"((a)[2]), "r"((a)[3]),                   \
          "r"((b)[0]), "r"((b)[1]))

// split 8 consecutive fp32 into 8 bf16 hi + 8 bf16 lo (packed)
__device__ __forceinline__ void split8(const float4 a, const float4 b,
                                       uint4& h, uint4& l) {
    __nv_bfloat162 h0 = __floats2bfloat162_rn(a.x, a.y);
    __nv_bfloat162 h1 = __floats2bfloat162_rn(a.z, a.w);
    __nv_bfloat162 h2 = __floats2bfloat162_rn(b.x, b.y);
    __nv_bfloat162 h3 = __floats2bfloat162_rn(b.z, b.w);
    float2 f0 = __bfloat1622float2(h0), f1 = __bfloat1622float2(h1);
    float2 f2 = __bfloat1622float2(h2), f3 = __bfloat1622float2(h3);
    __nv_bfloat162 l0 = __floats2bfloat162_rn(a.x - f0.x, a.y - f0.y);
    __nv_bfloat162 l1 = __floats2bfloat162_rn(a.z - f1.x, a.w - f1.y);
    __nv_bfloat162 l2 = __floats2bfloat162_rn(b.x - f2.x, b.y - f2.y);
    __nv_bfloat162 l3 = __floats2bfloat162_rn(b.z - f3.x, b.w - f3.y);
    h.x = *(uint32_t*)&h0; h.y = *(uint32_t*)&h1;
    h.z = *(uint32_t*)&h2; h.w = *(uint32_t*)&h3;
    l.x = *(uint32_t*)&l0; l.y = *(uint32_t*)&l1;
    l.z = *(uint32_t*)&l2; l.w = *(uint32_t*)&l3;
}

// ---------------------------------------------------------------------------
// Prep: transpose + bf16-split W[H,E] -> Wt_hi/Wt_lo [E][H]
// ---------------------------------------------------------------------------
__global__ void prep_w_kernel(const float* __restrict__ w) {
    __shared__ float t[32][33];
    const int k0 = blockIdx.x * 32, e0 = blockIdx.y * 32;
    const int tx = threadIdx.x, ty = threadIdx.y;
#pragma unroll
    for (int i = 0; i < 4; i++)
        t[ty + i * 8][tx] = w[(size_t)(k0 + ty + i * 8) * NEXP + e0 + tx];
    __syncthreads();
#pragma unroll
    for (int i = 0; i < 4; i++) {
        const int e = e0 + ty + i * 8, k = k0 + tx;
        const float v = t[tx][ty + i * 8];
        const __nv_bfloat16 h = __float2bfloat16(v);
        g_wt_hi[(size_t)e * HDIM + k] = h;
        g_wt_lo[(size_t)e * HDIM + k] = __float2bfloat16(v - __bfloat162float(h));
    }
}

// ---------------------------------------------------------------------------
// GEMM: logits = x @ W via mma.sync bf16 (3-term split), 2-stage pipeline
// CTA 128x128, 8 warps (warp tile 64x32), BK=32.
// ---------------------------------------------------------------------------
__global__ __launch_bounds__(256, 1) void gemm_mma_kernel(const float* __restrict__ x)
{
    extern __shared__ __nv_bfloat16 smem[];
    const uint32_t sb = smem_u32(smem);

    const int tid  = threadIdx.x;
    const int lane = tid & 31;
    const int wid  = tid >> 5;
    const int row0 = blockIdx.x * BM;
    const int col0 = blockIdx.y * BN;

    const int wm = (wid & 1) * 64;     // warp M base
    const int wn = (wid >> 1) * 32;    // warp N base

    // global-load mapping: thread covers 16 elems of one row
    const int r   = tid >> 1;          // 0..127
    const int c16 = (tid & 1) * 16;    // 0 or 16
    const float*         xrow  = x       + (size_t)(row0 + r) * HDIM + c16;
    const __nv_bfloat16* whrow = g_wt_hi + (size_t)(col0 + r) * HDIM + c16;
    const __nv_bfloat16* wlrow = g_wt_lo + (size_t)(col0 + r) * HDIM + c16;
    const uint32_t st_off = ((uint32_t)r * STRIDE + (uint32_t)c16) * 2;  // bytes

    // ldmatrix byte offsets (stage-relative)
    uint32_t aoff[4], boff[2];
    {
        const int ar = wm + (lane & 15);
        const int ac = (lane >> 4) * 8;
#pragma unroll
        for (int mt = 0; mt < 4; mt++)
            aoff[mt] = (uint32_t)((OFF_AHI + (ar + mt * 16) * STRIDE + ac) * 2);
        const int brr = (lane & 7) + ((lane >> 4) & 1) * 8;
        const int bc  = ((lane >> 3) & 1) * 8;
#pragma unroll
        for (int p = 0; p < 2; p++)
            boff[p] = (uint32_t)((OFF_BHI + (wn + p * 16 + brr) * STRIDE + bc) * 2);
    }

    float acc[4][4][4];
#pragma unroll
    for (int i = 0; i < 4; i++)
#pragma unroll
        for (int j = 0; j < 4; j++)
#pragma unroll
            for (int q = 0; q < 4; q++) acc[i][j][q] = 0.0f;

    // ---- prologue: fill stage 0 ----
    {
        float4 xv[4]; uint4 bh[2], bl[2];
        const float4* xp = (const float4*)xrow;
#pragma unroll
        for (int i = 0; i < 4; i++) xv[i] = xp[i];
        const uint4* hp = (const uint4*)whrow;
        const uint4* lp = (const uint4*)wlrow;
        bh[0] = hp[0]; bh[1] = hp[1]; bl[0] = lp[0]; bl[1] = lp[1];

        char* s = (char*)smem;
        uint4 h01, l01, h23, l23;
        split8(xv[0], xv[1], h01, l01);
        split8(xv[2], xv[3], h23, l23);
        *(uint4*)(s + OFF_AHI * 2 + st_off)      = h01;
        *(uint4*)(s + OFF_AHI * 2 + st_off + 16) = h23;
        *(uint4*)(s + OFF_ALO * 2 + st_off)      = l01;
        *(uint4*)(s + OFF_ALO * 2 + st_off + 16) = l23;
        *(uint4*)(s + OFF_BHI * 2 + st_off)      = bh[0];
        *(uint4*)(s + OFF_BHI * 2 + st_off + 16) = bh[1];
        *(uint4*)(s + OFF_BLO * 2 + st_off)      = bl[0];
        *(uint4*)(s + OFF_BLO * 2 + st_off + 16) = bl[1];
    }
    __syncthreads();

    // ---- main loop ----
    for (int t = 0; t < NT; ++t) {
        const int cur = t & 1;

        // issue next-stage global loads early (latency covered by compute)
        float4 xv[4]; uint4 bh[2], bl[2];
        if (t + 1 < NT) {
            const float4* xp = (const float4*)(xrow + (t + 1) * BK);
#pragma unroll
            for (int i = 0; i < 4; i++) xv[i] = xp[i];
            const uint4* hp = (const uint4*)(whrow + (t + 1) * BK);
            const uint4* lp = (const uint4*)(wlrow + (t + 1) * BK);
            bh[0] = hp[0]; bh[1] = hp[1]; bl[0] = lp[0]; bl[1] = lp[1];
        }

        // compute stage cur
        const uint32_t sbase = sb + (uint32_t)cur * STAGE_BYTES;
#pragma unroll
        for (int ks = 0; ks < 2; ks++) {
            uint32_t a_hi[4][4], a_lo[4][4], b_hi[2][4], b_lo[2][4];
#pragma unroll
            for (int mt = 0; mt < 4; mt++) {
                LDSM_X4(a_hi[mt], sbase + aoff[mt] + ks * 32);
                LDSM_X4(a_lo[mt], sbase + aoff[mt] + ks * 32 + (OFF_ALO - OFF_AHI) * 2);
            }
#pragma unroll
            for (int p = 0; p < 2; p++) {
                LDSM_X4(b_hi[p], sbase + boff[p] + ks * 32);
                LDSM_X4(b_lo[p], sbase + boff[p] + ks * 32 + (OFF_BLO - OFF_BHI) * 2);
            }
#pragma unroll
            for (int mt = 0; mt < 4; mt++)
#pragma unroll
                for (int nt = 0; nt < 4; nt++) {
                    MMA_BF16(acc[mt][nt], a_hi[mt], &b_hi[nt >> 1][(nt & 1) * 2]);
                    MMA_BF16(acc[mt][nt], a_lo[mt], &b_hi[nt >> 1][(nt & 1) * 2]);
                    MMA_BF16(acc[mt][nt], a_hi[mt], &b_lo[nt >> 1][(nt & 1) * 2]);
                }
        }

        // store next stage
        if (t + 1 < NT) {
            char* s = (char*)smem + (cur ^ 1) * STAGE_BYTES;
            uint4 h01, l01, h23, l23;
            split8(xv[0], xv[1], h01, l01);
            split8(xv[2], xv[3], h23, l23);
            *(uint4*)(s + OFF_AHI * 2 + st_off)      = h01;
            *(uint4*)(s + OFF_AHI * 2 + st_off + 16) = h23;
            *(uint4*)(s + OFF_ALO * 2 + st_off)      = l01;
            *(uint4*)(s + OFF_ALO * 2 + st_off + 16) = l23;
            *(uint4*)(s + OFF_BHI * 2 + st_off)      = bh[0];
            *(uint4*)(s + OFF_BHI * 2 + st_off + 16) = bh[1];
            *(uint4*)(s + OFF_BLO * 2 + st_off)      = bl[0];
            *(uint4*)(s + OFF_BLO * 2 + st_off + 16) = bl[1];
        }
        __syncthreads();
    }

    // ---- epilogue: accumulators -> g_logits ----
    const int erow = lane >> 2;             // 0..7
    const int ecol = (lane & 3) * 2;        // 0,2,4,6
#pragma unroll
    for (int mt = 0; mt < 4; mt++) {
        const int rbase = row0 + wm + mt * 16 + erow;
#pragma unroll
        for (int nt = 0; nt < 4; nt++) {
            const int c = col0 + wn + nt * 8 + ecol;
            float* d0 = g_logits + (size_t)rbase * NEXP + c;
            float* d1 = d0 + 8 * NEXP;
            d0[0] = acc[mt][nt][0]; d0[1] = acc[mt][nt][1];
            d1[0] = acc[mt][nt][2]; d1[1] = acc[mt][nt][3];
        }
    }
}

// ---------------------------------------------------------------------------
// Routing: one warp per token; expert e = j*32 + lane (slot j == group j).
// Reproduces jax.lax.top_k tie-break (lower index wins).
// ---------------------------------------------------------------------------
__global__ __launch_bounds__(256) void route_kernel(
    const float* __restrict__ bias, float* __restrict__ out)
{
    __shared__ float s_sh[8][NEXP];

    const int lane = threadIdx.x & 31;
    const int wrp  = threadIdx.x >> 5;
    const int t    = blockIdx.x * 8 + wrp;

    const float* lrow = g_logits + (size_t)t * NEXP;

    float v[8];
#pragma unroll
    for (int j = 0; j < 8; j++) v[j] = lrow[j * 32 + lane];

    float m = v[0];
#pragma unroll
    for (int j = 1; j < 8; j++) m = fmaxf(m, v[j]);
    for (int off = 16; off; off >>= 1)
        m = fmaxf(m, __shfl_xor_sync(0xffffffffu, m, off));

    float sum = 0.0f;
#pragma unroll
    for (int j = 0; j < 8; j++) { v[j] = __expf(v[j] - m); sum += v[j]; }
    for (int off = 16; off; off >>= 1)
        sum += __shfl_xor_sync(0xffffffffu, sum, off);
    const float inv = 1.0f / sum;

    float s[8], swb[8];
#pragma unroll
    for (int j = 0; j < 8; j++) {
        s[j] = v[j] * inv;
        s_sh[wrp][j * 32 + lane] = s[j];
        swb[j] = s[j] + bias[j * 32 + lane];
    }

    // group scores: top-2 sum within each 32-lane group
    float gs[8];
#pragma unroll
    for (int j = 0; j < 8; j++) {
        float hi = swb[j], lo = -INFINITY;
        for (int off = 16; off; off >>= 1) {
            float ohi = __shfl_xor_sync(0xffffffffu, hi, off);
            float olo = __shfl_xor_sync(0xffffffffu, lo, off);
            float nh = fmaxf(hi, ohi);
            float nl = fmaxf(fminf(hi, ohi), fmaxf(lo, olo));
            hi = nh; lo = nl;
        }
        gs[j] = hi + lo;
    }

    // top-4 groups by rank
    float mk[8];
#pragma unroll
    for (int g = 0; g < 8; g++) {
        int rank = 0;
#pragma unroll
        for (int k2 = 0; k2 < 8; k2++)
            if (gs[k2] > gs[g] || (gs[k2] == gs[g] && k2 < g)) rank++;
        mk[g] = (rank < 4) ? swb[g] : -INFINITY;
    }

    // iterative top-8
    float myv = 0.0f;
    int   myi = 0;
    float tot = 0.0f;
#pragma unroll
    for (int it = 0; it < NTOPK; it++) {
        float bv = mk[0];
        int   bi = lane;
#pragma unroll
        for (int j = 1; j < 8; j++) {
            const int idx = j * 32 + lane;
            if (mk[j] > bv || (mk[j] == bv && idx < bi)) { bv = mk[j]; bi = idx; }
        }
        for (int off = 16; off; off >>= 1) {
            float ov = __shfl_xor_sync(0xffffffffu, bv, off);
            int   oi = __shfl_xor_sync(0xffffffffu, bi, off);
            if (ov > bv || (ov == bv && oi < bi)) { bv = ov; bi = oi; }
        }
        const float ws = s_sh[wrp][bi];
        tot += ws;
        if (lane == it) { myv = ws; myi = bi; }
        if ((bi & 31) == lane) {
            const int jj = bi >> 5;
#pragma unroll
            for (int j = 0; j < 8; j++)
                if (j == jj) mk[j] = -INFINITY;
        }
    }

    const float itot = 1.0f / tot;
    if (lane < NTOPK) {
        out[(size_t)t * NTOPK + lane] = (myv * itot + 1e-20f) * 2.5f;
        out[(size_t)B_TOK * NTOPK + (size_t)t * NTOPK + lane] = (float)myi;
    }
}

// ---------------------------------------------------------------------------
extern "C" void kernel_launch(void* const* d_in, const int* in_sizes, int n_in,
                              void* d_out, int out_size)
{
    const float* x    = (const float*)d_in[0];   // [1,1,B,H]
    const float* w    = (const float*)d_in[1];   // [H,E]
    const float* bias = (const float*)d_in[2];   // [E]
    float* out = (float*)d_out;

    (void)cudaFuncSetAttribute(gemm_mma_kernel,
                               cudaFuncAttributeMaxDynamicSharedMemorySize, SMEM_DYN);

    prep_w_kernel<<<dim3(HDIM / 32, NEXP / 32), dim3(32, 8)>>>(w);
    gemm_mma_kernel<<<dim3(B_TOK / BM, NEXP / BN), 256, SMEM_DYN>>>(x);
    route_kernel<<<B_TOK / 8, 256>>>(bias, out);
}

// round 6
// speedup vs baseline: 1.0952x; 1.0952x over previous
#include <cuda_runtime.h>
#include <cuda_bf16.h>
#include <cstdint>
#include <math.h>

#define B_TOK 8192
#define HDIM  7168
#define NEXP  256
#define NTOPK 8

#define BM 128
#define BN 128
#define BK 32
#define NT (HDIM / BK)          // 224

#define STRIDE 40               // smem row stride in bf16 elems (pad 8)
#define TILE_B 10240u           // one 128x32 bf16 tile (STRIDE rows), bytes
#define A_STAGE 20480u          // hi tile + lo tile
#define B_STAGE 20480u
#define A_REGION (3u * A_STAGE) // 61440
#define SMEM_DYN (A_REGION + 4u * B_STAGE)  // 143360

// ---- device scratch (no cudaMalloc allowed) ----
__device__ float         g_logits[(size_t)B_TOK * NEXP];
__device__ __nv_bfloat16 g_wt_hi[(size_t)NEXP * HDIM];   // W^T hi  [E][H]
__device__ __nv_bfloat16 g_wt_lo[(size_t)NEXP * HDIM];   // W^T lo  [E][H]

__device__ __forceinline__ uint32_t smem_u32(const void* p) {
    uint32_t a;
    asm("{ .reg .u64 t; cvta.to.shared.u64 t, %1; cvt.u32.u64 %0, t; }" : "=r"(a) : "l"(p));
    return a;
}

#define LDSM_X4(d, addr)                                                        \
    asm volatile("ldmatrix.sync.aligned.m8n8.x4.shared.b16 {%0,%1,%2,%3}, [%4];"\
        : "=r"((d)[0]), "=r"((d)[1]), "=r"((d)[2]), "=r"((d)[3]) : "r"(addr))

#define MMA_BF16(c, a, b)                                                       \
    asm volatile("mma.sync.aligned.m16n8k16.row.col.f32.bf16.bf16.f32 "         \
        "{%0,%1,%2,%3}, {%4,%5,%6,%7}, {%8,%9}, {%0,%1,%2,%3};"                 \
        : "+f"((c)[0]), "+f"((c)[1]), "+f"((c)[2]), "+f"((c)[3])                \
        : "r"((a)[0]), "r"((a)[1]), "r"((a)[2]), "r"((a)[3]),                   \
          "r"((b)[0]), "r"((b)[1]))

#define CP16(dst, src)                                                          \
    asm volatile("cp.async.cg.shared.global [%0], [%1], 16;"                    \
                 :: "r"(dst), "l"(src) : "memory")
#define CP_COMMIT() asm volatile("cp.async.commit_group;" ::: "memory")
#define CP_WAIT2()  asm volatile("cp.async.wait_group 2;" ::: "memory")

// split 8 consecutive fp32 into 8 bf16 hi + 8 bf16 lo (packed)
__device__ __forceinline__ void split8(const float4 a, const float4 b,
                                       uint4& h, uint4& l) {
    __nv_bfloat162 h0 = __floats2bfloat162_rn(a.x, a.y);
    __nv_bfloat162 h1 = __floats2bfloat162_rn(a.z, a.w);
    __nv_bfloat162 h2 = __floats2bfloat162_rn(b.x, b.y);
    __nv_bfloat162 h3 = __floats2bfloat162_rn(b.z, b.w);
    float2 f0 = __bfloat1622float2(h0), f1 = __bfloat1622float2(h1);
    float2 f2 = __bfloat1622float2(h2), f3 = __bfloat1622float2(h3);
    __nv_bfloat162 l0 = __floats2bfloat162_rn(a.x - f0.x, a.y - f0.y);
    __nv_bfloat162 l1 = __floats2bfloat162_rn(a.z - f1.x, a.w - f1.y);
    __nv_bfloat162 l2 = __floats2bfloat162_rn(b.x - f2.x, b.y - f2.y);
    __nv_bfloat162 l3 = __floats2bfloat162_rn(b.z - f3.x, b.w - f3.y);
    h.x = *(uint32_t*)&h0; h.y = *(uint32_t*)&h1;
    h.z = *(uint32_t*)&h2; h.w = *(uint32_t*)&h3;
    l.x = *(uint32_t*)&l0; l.y = *(uint32_t*)&l1;
    l.z = *(uint32_t*)&l2; l.w = *(uint32_t*)&l3;
}

// ---------------------------------------------------------------------------
// Prep: transpose + bf16-split W[H,E] -> Wt_hi/Wt_lo [E][H]
// ---------------------------------------------------------------------------
__global__ void prep_w_kernel(const float* __restrict__ w) {
    __shared__ float t[32][33];
    const int k0 = blockIdx.x * 32, e0 = blockIdx.y * 32;
    const int tx = threadIdx.x, ty = threadIdx.y;
#pragma unroll
    for (int i = 0; i < 4; i++)
        t[ty + i * 8][tx] = w[(size_t)(k0 + ty + i * 8) * NEXP + e0 + tx];
    __syncthreads();
#pragma unroll
    for (int i = 0; i < 4; i++) {
        const int e = e0 + ty + i * 8, k = k0 + tx;
        const float v = t[tx][ty + i * 8];
        const __nv_bfloat16 h = __float2bfloat16(v);
        g_wt_hi[(size_t)e * HDIM + k] = h;
        g_wt_lo[(size_t)e * HDIM + k] = __float2bfloat16(v - __bfloat162float(h));
    }
}

// ---------------------------------------------------------------------------
// GEMM: logits = x @ W via mma.sync bf16 (3-term split)
// A: 3-stage smem ring (register-staged fp32 loads + fused split).
// B: 4-stage smem ring fed by cp.async, prefetch 2 tiles ahead.
// ---------------------------------------------------------------------------
__global__ __launch_bounds__(256, 1) void gemm_mma_kernel(const float* __restrict__ x)
{
    extern __shared__ __nv_bfloat16 smem[];
    const uint32_t sb = smem_u32(smem);

    const int tid  = threadIdx.x;
    const int lane = tid & 31;
    const int wid  = tid >> 5;
    const int row0 = blockIdx.x * BM;
    const int col0 = blockIdx.y * BN;

    const int wm = (wid & 1) * 64;     // warp M base
    const int wn = (wid >> 1) * 32;    // warp N base

    // global-load mapping: thread covers 16 elems of one row
    const int r   = tid >> 1;          // 0..127
    const int c16 = (tid & 1) * 16;    // 0 or 16
    const float*         xrow  = x       + (size_t)(row0 + r) * HDIM + c16;
    const __nv_bfloat16* whrow = g_wt_hi + (size_t)(col0 + r) * HDIM + c16;
    const __nv_bfloat16* wlrow = g_wt_lo + (size_t)(col0 + r) * HDIM + c16;
    const uint32_t st_off = ((uint32_t)r * STRIDE + (uint32_t)c16) * 2;  // bytes

    // ldmatrix byte offsets (stage-relative; lo tile at +TILE_B)
    uint32_t aoff[4], boff[2];
    {
        const int ar = wm + (lane & 15);
        const int ac = (lane >> 4) * 8;
#pragma unroll
        for (int mt = 0; mt < 4; mt++)
            aoff[mt] = (uint32_t)(((ar + mt * 16) * STRIDE + ac) * 2);
        const int brr = (lane & 7) + ((lane >> 4) & 1) * 8;
        const int bc  = ((lane >> 3) & 1) * 8;
#pragma unroll
        for (int p = 0; p < 2; p++)
            boff[p] = (uint32_t)(((wn + p * 16 + brr) * STRIDE + bc) * 2);
    }

    float acc[4][4][4];
#pragma unroll
    for (int i = 0; i < 4; i++)
#pragma unroll
        for (int j = 0; j < 4; j++)
#pragma unroll
            for (int q = 0; q < 4; q++) acc[i][j][q] = 0.0f;

    // ---- prologue ----
    float4 xv[4];
    {
        // A(0): load, split, store into A stage 0
        const float4* xp = (const float4*)xrow;
#pragma unroll
        for (int i = 0; i < 4; i++) xv[i] = xp[i];
        char* s = (char*)smem;               // A stage 0
        uint4 h01, l01, h23, l23;
        split8(xv[0], xv[1], h01, l01);
        split8(xv[2], xv[3], h23, l23);
        *(uint4*)(s + st_off)              = h01;
        *(uint4*)(s + st_off + 16)         = h23;
        *(uint4*)(s + TILE_B + st_off)     = l01;
        *(uint4*)(s + TILE_B + st_off + 16)= l23;

        // B(0), B(1): cp.async, one commit group each
#pragma unroll
        for (int p = 0; p < 2; p++) {
            const uint32_t d = sb + A_REGION + (uint32_t)p * B_STAGE + st_off;
            const char* sh = (const char*)(whrow + p * BK);
            const char* sl = (const char*)(wlrow + p * BK);
            CP16(d,               sh);
            CP16(d + 16,          sh + 16);
            CP16(d + TILE_B,      sl);
            CP16(d + TILE_B + 16, sl + 16);
            CP_COMMIT();
        }

        // x(1) into registers
        const float4* xq = (const float4*)(xrow + BK);
#pragma unroll
        for (int i = 0; i < 4; i++) xv[i] = xq[i];
    }

    // ---- main loop ----
    for (int t = 0; t < NT; ++t) {
        // 1) store A(t+1) from registers into A stage (t+1)%3
        if (t + 1 < NT) {
            char* s = (char*)smem + ((t + 1) % 3) * A_STAGE;
            uint4 h01, l01, h23, l23;
            split8(xv[0], xv[1], h01, l01);
            split8(xv[2], xv[3], h23, l23);
            *(uint4*)(s + st_off)               = h01;
            *(uint4*)(s + st_off + 16)          = h23;
            *(uint4*)(s + TILE_B + st_off)      = l01;
            *(uint4*)(s + TILE_B + st_off + 16) = l23;
        }
        // 2) x(t+2) LDG into registers; 3) B(t+2) cp.async into B stage (t+2)%4
        if (t + 2 < NT) {
            const float4* xp = (const float4*)(xrow + (t + 2) * BK);
#pragma unroll
            for (int i = 0; i < 4; i++) xv[i] = xp[i];

            const uint32_t d = sb + A_REGION + (uint32_t)((t + 2) % 4) * B_STAGE + st_off;
            const char* sh = (const char*)(whrow + (t + 2) * BK);
            const char* sl = (const char*)(wlrow + (t + 2) * BK);
            CP16(d,               sh);
            CP16(d + 16,          sh + 16);
            CP16(d + TILE_B,      sl);
            CP16(d + TILE_B + 16, sl + 16);
        }
        CP_COMMIT();            // unconditional: keeps group indexing aligned
        CP_WAIT2();             // groups for tiles <= t complete
        __syncthreads();

        // 4) compute stage t
        const uint32_t abase = sb + (uint32_t)(t % 3) * A_STAGE;
        const uint32_t bbase = sb + A_REGION + (uint32_t)(t % 4) * B_STAGE;
#pragma unroll
        for (int ks = 0; ks < 2; ks++) {
            uint32_t a_hi[4][4], a_lo[4][4], b_hi[2][4], b_lo[2][4];
#pragma unroll
            for (int mt = 0; mt < 4; mt++) {
                LDSM_X4(a_hi[mt], abase + aoff[mt] + ks * 32);
                LDSM_X4(a_lo[mt], abase + aoff[mt] + ks * 32 + TILE_B);
            }
#pragma unroll
            for (int p = 0; p < 2; p++) {
                LDSM_X4(b_hi[p], bbase + boff[p] + ks * 32);
                LDSM_X4(b_lo[p], bbase + boff[p] + ks * 32 + TILE_B);
            }
#pragma unroll
            for (int mt = 0; mt < 4; mt++)
#pragma unroll
                for (int nt = 0; nt < 4; nt++) {
                    MMA_BF16(acc[mt][nt], a_hi[mt], &b_hi[nt >> 1][(nt & 1) * 2]);
                    MMA_BF16(acc[mt][nt], a_lo[mt], &b_hi[nt >> 1][(nt & 1) * 2]);
                    MMA_BF16(acc[mt][nt], a_hi[mt], &b_lo[nt >> 1][(nt & 1) * 2]);
                }
        }
    }

    // ---- epilogue: accumulators -> g_logits ----
    const int erow = lane >> 2;             // 0..7
    const int ecol = (lane & 3) * 2;        // 0,2,4,6
#pragma unroll
    for (int mt = 0; mt < 4; mt++) {
        const int rbase = row0 + wm + mt * 16 + erow;
#pragma unroll
        for (int nt = 0; nt < 4; nt++) {
            const int c = col0 + wn + nt * 8 + ecol;
            float* d0 = g_logits + (size_t)rbase * NEXP + c;
            float* d1 = d0 + 8 * NEXP;
            d0[0] = acc[mt][nt][0]; d0[1] = acc[mt][nt][1];
            d1[0] = acc[mt][nt][2]; d1[1] = acc[mt][nt][3];
        }
    }
}

// ---------------------------------------------------------------------------
// Routing: one warp per token; expert e = j*32 + lane (slot j == group j).
// Reproduces jax.lax.top_k tie-break (lower index wins).
// ---------------------------------------------------------------------------
__global__ __launch_bounds__(256) void route_kernel(
    const float* __restrict__ bias, float* __restrict__ out)
{
    __shared__ float s_sh[8][NEXP];

    const int lane = threadIdx.x & 31;
    const int wrp  = threadIdx.x >> 5;
    const int t    = blockIdx.x * 8 + wrp;

    const float* lrow = g_logits + (size_t)t * NEXP;

    float v[8];
#pragma unroll
    for (int j = 0; j < 8; j++) v[j] = lrow[j * 32 + lane];

    float m = v[0];
#pragma unroll
    for (int j = 1; j < 8; j++) m = fmaxf(m, v[j]);
    for (int off = 16; off; off >>= 1)
        m = fmaxf(m, __shfl_xor_sync(0xffffffffu, m, off));

    float sum = 0.0f;
#pragma unroll
    for (int j = 0; j < 8; j++) { v[j] = __expf(v[j] - m); sum += v[j]; }
    for (int off = 16; off; off >>= 1)
        sum += __shfl_xor_sync(0xffffffffu, sum, off);
    const float inv = 1.0f / sum;

    float s[8], swb[8];
#pragma unroll
    for (int j = 0; j < 8; j++) {
        s[j] = v[j] * inv;
        s_sh[wrp][j * 32 + lane] = s[j];
        swb[j] = s[j] + bias[j * 32 + lane];
    }

    // group scores: top-2 sum within each 32-lane group
    float gs[8];
#pragma unroll
    for (int j = 0; j < 8; j++) {
        float hi = swb[j], lo = -INFINITY;
        for (int off = 16; off; off >>= 1) {
            float ohi = __shfl_xor_sync(0xffffffffu, hi, off);
            float olo = __shfl_xor_sync(0xffffffffu, lo, off);
            float nh = fmaxf(hi, ohi);
            float nl = fmaxf(fminf(hi, ohi), fmaxf(lo, olo));
            hi = nh; lo = nl;
        }
        gs[j] = hi + lo;
    }

    // top-4 groups by rank
    float mk[8];
#pragma unroll
    for (int g = 0; g < 8; g++) {
        int rank = 0;
#pragma unroll
        for (int k2 = 0; k2 < 8; k2++)
            if (gs[k2] > gs[g] || (gs[k2] == gs[g] && k2 < g)) rank++;
        mk[g] = (rank < 4) ? swb[g] : -INFINITY;
    }

    // iterative top-8
    float myv = 0.0f;
    int   myi = 0;
    float tot = 0.0f;
#pragma unroll
    for (int it = 0; it < NTOPK; it++) {
        float bv = mk[0];
        int   bi = lane;
#pragma unroll
        for (int j = 1; j < 8; j++) {
            const int idx = j * 32 + lane;
            if (mk[j] > bv || (mk[j] == bv && idx < bi)) { bv = mk[j]; bi = idx; }
        }
        for (int off = 16; off; off >>= 1) {
            float ov = __shfl_xor_sync(0xffffffffu, bv, off);
            int   oi = __shfl_xor_sync(0xffffffffu, bi, off);
            if (ov > bv || (ov == bv && oi < bi)) { bv = ov; bi = oi; }
        }
        const float ws = s_sh[wrp][bi];
        tot += ws;
        if (lane == it) { myv = ws; myi = bi; }
        if ((bi & 31) == lane) {
            const int jj = bi >> 5;
#pragma unroll
            for (int j = 0; j < 8; j++)
                if (j == jj) mk[j] = -INFINITY;
        }
    }

    const float itot = 1.0f / tot;
    if (lane < NTOPK) {
        out[(size_t)t * NTOPK + lane] = (myv * itot + 1e-20f) * 2.5f;
        out[(size_t)B_TOK * NTOPK + (size_t)t * NTOPK + lane] = (float)myi;
    }
}

// ---------------------------------------------------------------------------
extern "C" void kernel_launch(void* const* d_in, const int* in_sizes, int n_in,
                              void* d_out, int out_size)
{
    const float* x    = (const float*)d_in[0];   // [1,1,B,H]
    const float* w    = (const float*)d_in[1];   // [H,E]
    const float* bias = (const float*)d_in[2];   // [E]
    float* out = (float*)d_out;

    (void)cudaFuncSetAttribute(gemm_mma_kernel,
                               cudaFuncAttributeMaxDynamicSharedMemorySize, SMEM_DYN);

    prep_w_kernel<<<dim3(HDIM / 32, NEXP / 32), dim3(32, 8)>>>(w);
    gemm_mma_kernel<<<dim3(B_TOK / BM, NEXP / BN), 256, SMEM_DYN>>>(x);
    route_kernel<<<B_TOK / 8, 256>>>(bias, out);
}